// round 1
// baseline (speedup 1.0000x reference)
#include <cuda_runtime.h>

#define NN 50000
#define NE 200000
#define ET 250000   // edges + self loops
#define IC 14
#define HD 128
#define NH 8
#define OD 4
#define NS 0.2f

// ---- scratch (static __device__ arrays; no allocations) ----
__device__ int    g_deg[NN];
__device__ int    g_rowptr[NN + 1];
__device__ int    g_cursor[NN];
__device__ int    g_col[ET];
__device__ float  g_vs[IC * NH];
__device__ float  g_vd[IC * NH];
__device__ float  g_as[NN * NH];
__device__ float  g_ad[NN * NH];
__device__ float4 g_h2[NN];
__device__ float  g_a2s[NN];
__device__ float  g_a2d[NN];
__device__ int    g_is64;

// ---- edge-index dtype detection: int64 iff every high 32-bit word is zero ----
__global__ void k_detect(const int* __restrict__ p) {
    __shared__ int ok;
    if (threadIdx.x == 0) ok = 1;
    __syncthreads();
    // Check elements [0, NE): if buffer is int64, word 2i+1 is the high half.
    // Safe even if buffer is int32 (we touch words < 2*NE <= element count).
    for (int i = threadIdx.x; i < NE; i += blockDim.x) {
        if (p[2 * i + 1] != 0) { ok = 0; break; }
    }
    __syncthreads();
    if (threadIdx.x == 0) g_is64 = ok;
}

__device__ __forceinline__ int load_edge(const void* ei, int idx, int is64) {
    if (is64) return (int)((const long long*)ei)[idx];
    return ((const int*)ei)[idx];
}

__global__ void k_zero() {
    int i = blockIdx.x * blockDim.x + threadIdx.x;
    if (i < NN) g_deg[i] = 0;
}

__global__ void k_hist(const void* __restrict__ ei) {
    int i = blockIdx.x * blockDim.x + threadIdx.x;
    if (i >= ET) return;
    int is64 = g_is64;
    int dst = (i < NE) ? load_edge(ei, NE + i, is64) : (i - NE);
    atomicAdd(&g_deg[dst], 1);
}

__global__ void k_scan() {
    __shared__ int sh[1024];
    const int T = 1024;
    int t = threadIdx.x;
    const int chunk = (NN + T - 1) / T;
    int beg = t * chunk;
    int end = beg + chunk;
    if (beg > NN) beg = NN;
    if (end > NN) end = NN;
    int s = 0;
    for (int i = beg; i < end; i++) s += g_deg[i];
    sh[t] = s;
    __syncthreads();
    for (int off = 1; off < T; off <<= 1) {
        int v = (t >= off) ? sh[t - off] : 0;
        __syncthreads();
        sh[t] += v;
        __syncthreads();
    }
    int run = sh[t] - s;  // exclusive prefix for this thread's chunk
    for (int i = beg; i < end; i++) {
        g_rowptr[i] = run;
        g_cursor[i] = run;
        run += g_deg[i];
    }
    if (t == T - 1) g_rowptr[NN] = sh[T - 1];
}

__global__ void k_scatter(const void* __restrict__ ei) {
    int i = blockIdx.x * blockDim.x + threadIdx.x;
    if (i >= ET) return;
    int is64 = g_is64;
    int src, dst;
    if (i < NE) {
        src = load_edge(ei, i, is64);
        dst = load_edge(ei, NE + i, is64);
    } else {
        src = i - NE;
        dst = i - NE;
    }
    int pos = atomicAdd(&g_cursor[dst], 1);
    g_col[pos] = src;
}

// v_s[c][h] = sum_f W1[c, h*HD+f] * att_src1[h,f]   (and v_d with att_dst1)
__global__ void k_vsd(const float* __restrict__ W1,
                      const float* __restrict__ as1,
                      const float* __restrict__ ad1) {
    int idx = threadIdx.x;
    if (idx >= IC * NH) return;
    int c = idx / NH, h = idx % NH;
    float s = 0.f, d = 0.f;
    for (int f = 0; f < HD; f++) {
        float w = W1[c * (NH * HD) + h * HD + f];
        s = fmaf(w, as1[h * HD + f], s);
        d = fmaf(w, ad1[h * HD + f], d);
    }
    g_vs[c * NH + h] = s;
    g_vd[c * NH + h] = d;
}

// alpha_src[n,h] = x[n] . v_s[:,h] ; alpha_dst[n,h] = x[n] . v_d[:,h]
__global__ void k_alpha(const float* __restrict__ x) {
    __shared__ float vs[IC * NH], vd[IC * NH];
    for (int i = threadIdx.x; i < IC * NH; i += blockDim.x) {
        vs[i] = g_vs[i];
        vd[i] = g_vd[i];
    }
    __syncthreads();
    int n = blockIdx.x * blockDim.x + threadIdx.x;
    if (n >= NN) return;
    float xr[IC];
#pragma unroll
    for (int c = 0; c < IC; c++) xr[c] = x[n * IC + c];
#pragma unroll
    for (int h = 0; h < NH; h++) {
        float s = 0.f, d = 0.f;
#pragma unroll
        for (int c = 0; c < IC; c++) {
            s = fmaf(xr[c], vs[c * NH + h], s);
            d = fmaf(xr[c], vd[c * NH + h], d);
        }
        g_as[n * NH + h] = s;
        g_ad[n * NH + h] = d;
    }
}

// Fused: layer-1 softmax aggregation (via weighted x sums) -> project through
// W1 -> +b1 -> ELU -> project through W2 -> h2[n,0..3], and layer-2 attention
// scalars a2s/a2d. One block per node (grid-stride); warp w = head w.
__global__ void __launch_bounds__(256, 2)
k_layer1(const float* __restrict__ x, const float* __restrict__ W1,
         const float* __restrict__ b1, const float* __restrict__ W2,
         const float* __restrict__ as2, const float* __restrict__ ad2) {
    const int tid = threadIdx.x;
    const int warp = tid >> 5;   // 0..7 == head
    const int lane = tid & 31;

    // Per-thread weight slices: thread owns output features o = tid*4 + k.
    float w1r[IC * 4];
#pragma unroll
    for (int c = 0; c < IC; c++)
#pragma unroll
        for (int k = 0; k < 4; k++)
            w1r[c * 4 + k] = W1[c * (NH * HD) + tid * 4 + k];
    float w2r[4 * OD];
#pragma unroll
    for (int k = 0; k < 4; k++)
#pragma unroll
        for (int j = 0; j < OD; j++)
            w2r[k * OD + j] = W2[(tid * 4 + k) * OD + j];
    float b1r[4];
#pragma unroll
    for (int k = 0; k < 4; k++) b1r[k] = b1[tid * 4 + k];
    float as2r[OD], ad2r[OD];
#pragma unroll
    for (int j = 0; j < OD; j++) { as2r[j] = as2[j]; ad2r[j] = ad2[j]; }

    __shared__ float zsh[NH][IC];
    __shared__ float red[8][OD];
    __shared__ float h2sh[OD];

    for (int n = blockIdx.x; n < NN; n += gridDim.x) {
        const int r0 = g_rowptr[n], r1 = g_rowptr[n + 1];
        {
            const int h = warp;
            const float adn = g_ad[n * NH + h];
            float m = -1e30f;
            for (int e = r0 + lane; e < r1; e += 32) {
                int s = g_col[e];
                float v = g_as[s * NH + h] + adn;
                v = (v >= 0.f) ? v : NS * v;
                m = fmaxf(m, v);
            }
#pragma unroll
            for (int o = 16; o; o >>= 1)
                m = fmaxf(m, __shfl_xor_sync(0xffffffffu, m, o));
            float ss = 0.f;
            float zc[IC];
#pragma unroll
            for (int c = 0; c < IC; c++) zc[c] = 0.f;
            for (int e = r0 + lane; e < r1; e += 32) {
                int s = g_col[e];
                float v = g_as[s * NH + h] + adn;
                v = (v >= 0.f) ? v : NS * v;
                float w = __expf(v - m);
                ss += w;
                const float* xp = x + s * IC;
#pragma unroll
                for (int c = 0; c < IC; c++) zc[c] = fmaf(w, __ldg(xp + c), zc[c]);
            }
#pragma unroll
            for (int o = 16; o; o >>= 1) {
                ss += __shfl_xor_sync(0xffffffffu, ss, o);
#pragma unroll
                for (int c = 0; c < IC; c++)
                    zc[c] += __shfl_xor_sync(0xffffffffu, zc[c], o);
            }
            if (lane == 0) {
                float inv = 1.f / (ss + 1e-16f);
#pragma unroll
                for (int c = 0; c < IC; c++) zsh[h][c] = zc[c] * inv;
            }
        }
        __syncthreads();

        // projection: out[o] = z[h].W1[:,o] + b1[o]; a = elu; h2 += a*W2[o,:]
        float zl[IC];
#pragma unroll
        for (int c = 0; c < IC; c++) zl[c] = zsh[warp][c];
        float hp[OD];
#pragma unroll
        for (int j = 0; j < OD; j++) hp[j] = 0.f;
#pragma unroll
        for (int k = 0; k < 4; k++) {
            float t = b1r[k];
#pragma unroll
            for (int c = 0; c < IC; c++) t = fmaf(zl[c], w1r[c * 4 + k], t);
            float a = (t > 0.f) ? t : (__expf(t) - 1.f);
#pragma unroll
            for (int j = 0; j < OD; j++) hp[j] = fmaf(a, w2r[k * OD + j], hp[j]);
        }
#pragma unroll
        for (int j = 0; j < OD; j++)
#pragma unroll
            for (int o = 16; o; o >>= 1)
                hp[j] += __shfl_xor_sync(0xffffffffu, hp[j], o);
        if (lane == 0) {
#pragma unroll
            for (int j = 0; j < OD; j++) red[warp][j] = hp[j];
        }
        __syncthreads();
        if (tid < OD) {
            float s = 0.f;
#pragma unroll
            for (int w = 0; w < 8; w++) s += red[w][tid];
            h2sh[tid] = s;
            ((float*)&g_h2[n])[tid] = s;
        }
        __syncthreads();
        if (tid == 0) {
            float s = 0.f, d = 0.f;
#pragma unroll
            for (int j = 0; j < OD; j++) {
                s = fmaf(h2sh[j], as2r[j], s);
                d = fmaf(h2sh[j], ad2r[j], d);
            }
            g_a2s[n] = s;
            g_a2d[n] = d;
        }
        __syncthreads();  // protect zsh/red/h2sh before next node
    }
}

// Layer-2: warp per destination node. heads=1, F=4, mean over heads = identity.
__global__ void k_layer2(float* __restrict__ out, const float* __restrict__ b2) {
    int gw = (blockIdx.x * blockDim.x + threadIdx.x) >> 5;
    int lane = threadIdx.x & 31;
    if (gw >= NN) return;
    const int n = gw;
    const int r0 = g_rowptr[n], r1 = g_rowptr[n + 1];
    const float adn = g_a2d[n];
    float m = -1e30f;
    for (int e = r0 + lane; e < r1; e += 32) {
        int s = g_col[e];
        float v = g_a2s[s] + adn;
        v = (v >= 0.f) ? v : NS * v;
        m = fmaxf(m, v);
    }
#pragma unroll
    for (int o = 16; o; o >>= 1) m = fmaxf(m, __shfl_xor_sync(0xffffffffu, m, o));
    float ss = 0.f;
    float ax = 0.f, ay = 0.f, az = 0.f, aw = 0.f;
    for (int e = r0 + lane; e < r1; e += 32) {
        int s = g_col[e];
        float v = g_a2s[s] + adn;
        v = (v >= 0.f) ? v : NS * v;
        float w = __expf(v - m);
        ss += w;
        float4 hv = g_h2[s];
        ax = fmaf(w, hv.x, ax);
        ay = fmaf(w, hv.y, ay);
        az = fmaf(w, hv.z, az);
        aw = fmaf(w, hv.w, aw);
    }
#pragma unroll
    for (int o = 16; o; o >>= 1) {
        ss += __shfl_xor_sync(0xffffffffu, ss, o);
        ax += __shfl_xor_sync(0xffffffffu, ax, o);
        ay += __shfl_xor_sync(0xffffffffu, ay, o);
        az += __shfl_xor_sync(0xffffffffu, az, o);
        aw += __shfl_xor_sync(0xffffffffu, aw, o);
    }
    if (lane == 0) {
        float inv = 1.f / (ss + 1e-16f);
        float4 o4;
        o4.x = ax * inv + b2[0];
        o4.y = ay * inv + b2[1];
        o4.z = az * inv + b2[2];
        o4.w = aw * inv + b2[3];
        ((float4*)out)[n] = o4;
    }
}

extern "C" void kernel_launch(void* const* d_in, const int* in_sizes, int n_in,
                              void* d_out, int out_size) {
    const float* x   = (const float*)d_in[0];
    const void*  ei  = d_in[1];
    const float* W1  = (const float*)d_in[2];
    const float* as1 = (const float*)d_in[3];
    const float* ad1 = (const float*)d_in[4];
    const float* b1  = (const float*)d_in[5];
    const float* W2  = (const float*)d_in[6];
    const float* as2 = (const float*)d_in[7];
    const float* ad2 = (const float*)d_in[8];
    const float* b2  = (const float*)d_in[9];
    float* out = (float*)d_out;

    k_detect<<<1, 1024>>>((const int*)ei);
    k_zero<<<(NN + 255) / 256, 256>>>();
    k_hist<<<(ET + 255) / 256, 256>>>(ei);
    k_scan<<<1, 1024>>>();
    k_scatter<<<(ET + 255) / 256, 256>>>(ei);
    k_vsd<<<1, 128>>>(W1, as1, ad1);
    k_alpha<<<(NN + 255) / 256, 256>>>(x);
    k_layer1<<<2048, 256>>>(x, W1, b1, W2, as2, ad2);
    k_layer2<<<(NN * 32 + 255) / 256, 256>>>(out, b2);
}

// round 2
// speedup vs baseline: 2.3638x; 2.3638x over previous
#include <cuda_runtime.h>

#define NN 50000
#define NE 200000
#define ET 250000   // edges + self loops
#define IC 14
#define HD 128
#define NH 8
#define OD 4
#define NS 0.2f
#define NB 196      // scan blocks = ceil(NN/256)

// ---- scratch (static __device__ arrays; no allocations) ----
__device__ int    g_deg[NN];
__device__ int    g_rowptr[NN + 1];
__device__ int    g_cursor[NN];
__device__ int    g_col[ET];
__device__ int    g_bsum[NB];
__device__ int    g_boff[256];
__device__ float  g_vs[IC * NH];
__device__ float  g_vd[IC * NH];
__device__ float  g_as[NN * NH];
__device__ float  g_ad[NN * NH];
__device__ float  g_z[NN * NH * IC];
__device__ float4 g_h2[NN];
__device__ float  g_a2s[NN];
__device__ float  g_a2d[NN];
__device__ int    g_is64;

// ---- packed f32x2 helpers (Blackwell packed-FMA pipe) ----
__device__ __forceinline__ unsigned long long pk2(float lo, float hi) {
    unsigned long long r;
    asm("mov.b64 %0, {%1, %2};" : "=l"(r) : "f"(lo), "f"(hi));
    return r;
}
__device__ __forceinline__ void upk2(unsigned long long v, float& lo, float& hi) {
    asm("mov.b64 {%0, %1}, %2;" : "=f"(lo), "=f"(hi) : "l"(v));
}
__device__ __forceinline__ unsigned long long fma2(unsigned long long a,
                                                   unsigned long long b,
                                                   unsigned long long c) {
    unsigned long long d;
    asm("fma.rn.f32x2 %0, %1, %2, %3;" : "=l"(d) : "l"(a), "l"(b), "l"(c));
    return d;
}

__global__ void k_init() {
    int i = blockIdx.x * blockDim.x + threadIdx.x;
    if (i < NN) g_deg[i] = 0;
    if (i == 0) g_is64 = 1;
}

// int64 iff every high 32-bit word is zero (safe to read either way:
// words touched < 2*NE <= total word count of an int32 [2,NE] buffer)
__global__ void k_detect(const int* __restrict__ p) {
    int i = blockIdx.x * blockDim.x + threadIdx.x;
    if (i < NE && p[2 * i + 1] != 0) g_is64 = 0;
}

__device__ __forceinline__ int load_edge(const void* ei, int idx, int is64) {
    if (is64) return (int)((const long long*)ei)[idx];
    return ((const int*)ei)[idx];
}

__global__ void k_hist(const void* __restrict__ ei) {
    int i = blockIdx.x * blockDim.x + threadIdx.x;
    if (i >= ET) return;
    int is64 = g_is64;
    int dst = (i < NE) ? load_edge(ei, NE + i, is64) : (i - NE);
    atomicAdd(&g_deg[dst], 1);
}

__device__ __forceinline__ int block_scan_256(int v, int t) {
    __shared__ int wt[8];
    int lane = t & 31, w = t >> 5;
    int s = v;
#pragma unroll
    for (int o = 1; o < 32; o <<= 1) {
        int u = __shfl_up_sync(0xffffffffu, s, o);
        if (lane >= o) s += u;
    }
    if (lane == 31) wt[w] = s;
    __syncthreads();
    if (t < 8) {
        int u = wt[t];
#pragma unroll
        for (int o = 1; o < 8; o <<= 1) {
            int x = __shfl_up_sync(0xffu, u, o);
            if (t >= o) u += x;
        }
        wt[t] = u;
    }
    __syncthreads();
    return s + (w > 0 ? wt[w - 1] : 0);  // inclusive scan
}

__global__ void k_scanA() {
    int t = threadIdx.x;
    int i = blockIdx.x * 256 + t;
    int v = (i < NN) ? g_deg[i] : 0;
    int incl = block_scan_256(v, t);
    if (i < NN) g_rowptr[i] = incl - v;  // exclusive within block
    if (t == 255) g_bsum[blockIdx.x] = incl;
}

__global__ void k_scanB() {
    int t = threadIdx.x;
    int v = (t < NB) ? g_bsum[t] : 0;
    int incl = block_scan_256(v, t);
    g_boff[t] = incl - v;
    if (t == NB - 1) g_rowptr[NN] = incl;
}

__global__ void k_scanC() {
    int i = blockIdx.x * 256 + threadIdx.x;
    if (i < NN) {
        int r = g_rowptr[i] + g_boff[blockIdx.x];
        g_rowptr[i] = r;
        g_cursor[i] = r;
    }
}

__global__ void k_scatter(const void* __restrict__ ei) {
    int i = blockIdx.x * blockDim.x + threadIdx.x;
    if (i >= ET) return;
    int is64 = g_is64;
    int src, dst;
    if (i < NE) {
        src = load_edge(ei, i, is64);
        dst = load_edge(ei, NE + i, is64);
    } else {
        src = i - NE;
        dst = i - NE;
    }
    int pos = atomicAdd(&g_cursor[dst], 1);
    g_col[pos] = src;
}

// v_s[c][h] = sum_f W1[c, h*HD+f] * att_src1[h,f]   (and v_d with att_dst1)
__global__ void k_vsd(const float* __restrict__ W1,
                      const float* __restrict__ as1,
                      const float* __restrict__ ad1) {
    int idx = threadIdx.x;
    if (idx >= IC * NH) return;
    int c = idx / NH, h = idx % NH;
    float s = 0.f, d = 0.f;
    for (int f = 0; f < HD; f++) {
        float w = W1[c * (NH * HD) + h * HD + f];
        s = fmaf(w, as1[h * HD + f], s);
        d = fmaf(w, ad1[h * HD + f], d);
    }
    g_vs[c * NH + h] = s;
    g_vd[c * NH + h] = d;
}

// alpha_src[n,h] = x[n] . v_s[:,h] ; alpha_dst[n,h] = x[n] . v_d[:,h]
__global__ void k_alpha(const float* __restrict__ x) {
    __shared__ float vs[IC * NH], vd[IC * NH];
    for (int i = threadIdx.x; i < IC * NH; i += blockDim.x) {
        vs[i] = g_vs[i];
        vd[i] = g_vd[i];
    }
    __syncthreads();
    int n = blockIdx.x * blockDim.x + threadIdx.x;
    if (n >= NN) return;
    float xr[IC];
#pragma unroll
    for (int c = 0; c < IC; c++) xr[c] = x[n * IC + c];
#pragma unroll
    for (int h = 0; h < NH; h++) {
        float s = 0.f, d = 0.f;
#pragma unroll
        for (int c = 0; c < IC; c++) {
            s = fmaf(xr[c], vs[c * NH + h], s);
            d = fmaf(xr[c], vd[c * NH + h], d);
        }
        g_as[n * NH + h] = s;
        g_ad[n * NH + h] = d;
    }
}

// Aggregation: one thread per (node, head). Softmax over in-edges, weighted
// sum of 14-dim x rows. No shuffles, no barriers — pure ILP over L2 loads.
__global__ void k_agg(const float* __restrict__ x) {
    int idx = blockIdx.x * blockDim.x + threadIdx.x;
    if (idx >= NN * NH) return;
    const int n = idx >> 3;     // NH == 8
    const int h = idx & 7;
    const int r0 = g_rowptr[n], r1 = g_rowptr[n + 1];
    const float adn = g_ad[n * NH + h];
    float m = -1e30f;
    for (int e = r0; e < r1; e++) {
        int s = g_col[e];
        float v = g_as[s * NH + h] + adn;
        v = (v >= 0.f) ? v : NS * v;
        m = fmaxf(m, v);
    }
    float ss = 0.f;
    float zc[IC];
#pragma unroll
    for (int c = 0; c < IC; c++) zc[c] = 0.f;
    for (int e = r0; e < r1; e++) {
        int s = g_col[e];
        float v = g_as[s * NH + h] + adn;
        v = (v >= 0.f) ? v : NS * v;
        float w = __expf(v - m);
        ss += w;
        const float* xp = x + s * IC;
#pragma unroll
        for (int c = 0; c < IC; c++) zc[c] = fmaf(w, __ldg(xp + c), zc[c]);
    }
    float inv = 1.f / (ss + 1e-16f);
    float* zp = g_z + idx * IC;
#pragma unroll
    for (int c = 0; c < IC; c++) zp[c] = zc[c] * inv;
}

// Projection: persistent blocks, weights in registers (packed f32x2).
// Per node: h1[o] = z[head(o)] . W1[:,o] + b1[o]; a = elu(h1);
// h2[j] = sum_o a[o]*W2[o,j]; also layer-2 attention scalars.
__global__ void __launch_bounds__(256, 2)
k_proj(const float* __restrict__ W1, const float* __restrict__ b1,
       const float* __restrict__ W2, const float* __restrict__ as2,
       const float* __restrict__ ad2) {
    const int tid = threadIdx.x;
    const int warp = tid >> 5;   // head
    const int lane = tid & 31;

    // thread owns outputs o = tid*4 + {0..3}; packed pairs (0,1) and (2,3)
    unsigned long long w1p[IC * 2];
#pragma unroll
    for (int c = 0; c < IC; c++) {
        const float* wr = W1 + c * (NH * HD) + tid * 4;
        w1p[c * 2 + 0] = pk2(wr[0], wr[1]);
        w1p[c * 2 + 1] = pk2(wr[2], wr[3]);
    }
    unsigned long long w2p[4 * 2];
#pragma unroll
    for (int k = 0; k < 4; k++) {
        const float* wr = W2 + (tid * 4 + k) * OD;
        w2p[k * 2 + 0] = pk2(wr[0], wr[1]);
        w2p[k * 2 + 1] = pk2(wr[2], wr[3]);
    }
    const unsigned long long b01 = pk2(b1[tid * 4 + 0], b1[tid * 4 + 1]);
    const unsigned long long b23 = pk2(b1[tid * 4 + 2], b1[tid * 4 + 3]);

    __shared__ float red[8][OD];
    __shared__ float h2sh[OD];

    for (int n = blockIdx.x; n < NN; n += gridDim.x) {
        // broadcast load of this head's z (same address across warp -> L1 bcast)
        const float* zp = g_z + (n * NH + warp) * IC;
        unsigned long long zz[IC];
#pragma unroll
        for (int c = 0; c < IC; c++) {
            float zv = __ldg(zp + c);
            zz[c] = pk2(zv, zv);
        }
        unsigned long long a01 = b01, a23 = b23;
#pragma unroll
        for (int c = 0; c < IC; c++) {
            a01 = fma2(zz[c], w1p[c * 2 + 0], a01);
            a23 = fma2(zz[c], w1p[c * 2 + 1], a23);
        }
        float t0, t1, t2, t3;
        upk2(a01, t0, t1);
        upk2(a23, t2, t3);
        t0 = (t0 > 0.f) ? t0 : (__expf(t0) - 1.f);
        t1 = (t1 > 0.f) ? t1 : (__expf(t1) - 1.f);
        t2 = (t2 > 0.f) ? t2 : (__expf(t2) - 1.f);
        t3 = (t3 > 0.f) ? t3 : (__expf(t3) - 1.f);
        unsigned long long h01 = pk2(0.f, 0.f), h23 = pk2(0.f, 0.f);
        {
            unsigned long long aa;
            aa = pk2(t0, t0);
            h01 = fma2(aa, w2p[0], h01); h23 = fma2(aa, w2p[1], h23);
            aa = pk2(t1, t1);
            h01 = fma2(aa, w2p[2], h01); h23 = fma2(aa, w2p[3], h23);
            aa = pk2(t2, t2);
            h01 = fma2(aa, w2p[4], h01); h23 = fma2(aa, w2p[5], h23);
            aa = pk2(t3, t3);
            h01 = fma2(aa, w2p[6], h01); h23 = fma2(aa, w2p[7], h23);
        }
        float hx, hy, hz, hw;
        upk2(h01, hx, hy);
        upk2(h23, hz, hw);
#pragma unroll
        for (int o = 16; o; o >>= 1) {
            hx += __shfl_xor_sync(0xffffffffu, hx, o);
            hy += __shfl_xor_sync(0xffffffffu, hy, o);
            hz += __shfl_xor_sync(0xffffffffu, hz, o);
            hw += __shfl_xor_sync(0xffffffffu, hw, o);
        }
        if (lane == 0) {
            red[warp][0] = hx; red[warp][1] = hy;
            red[warp][2] = hz; red[warp][3] = hw;
        }
        __syncthreads();
        if (tid < OD) {
            float s = 0.f;
#pragma unroll
            for (int w = 0; w < 8; w++) s += red[w][tid];
            h2sh[tid] = s;
            ((float*)&g_h2[n])[tid] = s;
        }
        __syncthreads();
        if (tid == 0) {
            float s = 0.f, d = 0.f;
#pragma unroll
            for (int j = 0; j < OD; j++) {
                s = fmaf(h2sh[j], __ldg(as2 + j), s);
                d = fmaf(h2sh[j], __ldg(ad2 + j), d);
            }
            g_a2s[n] = s;
            g_a2d[n] = d;
        }
        // red/h2sh reuse is protected by the first __syncthreads of next iter
        // for red; h2sh readers (tid==0) finish before writers can pass the
        // next first barrier.
    }
}

// Layer-2: warp per destination node (heads=1, F=4, mean over heads = identity)
__global__ void k_layer2(float* __restrict__ out, const float* __restrict__ b2) {
    int gw = (blockIdx.x * blockDim.x + threadIdx.x) >> 5;
    int lane = threadIdx.x & 31;
    if (gw >= NN) return;
    const int n = gw;
    const int r0 = g_rowptr[n], r1 = g_rowptr[n + 1];
    const float adn = g_a2d[n];
    float m = -1e30f;
    for (int e = r0 + lane; e < r1; e += 32) {
        int s = g_col[e];
        float v = g_a2s[s] + adn;
        v = (v >= 0.f) ? v : NS * v;
        m = fmaxf(m, v);
    }
#pragma unroll
    for (int o = 16; o; o >>= 1) m = fmaxf(m, __shfl_xor_sync(0xffffffffu, m, o));
    float ss = 0.f;
    float ax = 0.f, ay = 0.f, az = 0.f, aw = 0.f;
    for (int e = r0 + lane; e < r1; e += 32) {
        int s = g_col[e];
        float v = g_a2s[s] + adn;
        v = (v >= 0.f) ? v : NS * v;
        float w = __expf(v - m);
        ss += w;
        float4 hv = g_h2[s];
        ax = fmaf(w, hv.x, ax);
        ay = fmaf(w, hv.y, ay);
        az = fmaf(w, hv.z, az);
        aw = fmaf(w, hv.w, aw);
    }
#pragma unroll
    for (int o = 16; o; o >>= 1) {
        ss += __shfl_xor_sync(0xffffffffu, ss, o);
        ax += __shfl_xor_sync(0xffffffffu, ax, o);
        ay += __shfl_xor_sync(0xffffffffu, ay, o);
        az += __shfl_xor_sync(0xffffffffu, az, o);
        aw += __shfl_xor_sync(0xffffffffu, aw, o);
    }
    if (lane == 0) {
        float inv = 1.f / (ss + 1e-16f);
        float4 o4;
        o4.x = ax * inv + b2[0];
        o4.y = ay * inv + b2[1];
        o4.z = az * inv + b2[2];
        o4.w = aw * inv + b2[3];
        ((float4*)out)[n] = o4;
    }
}

extern "C" void kernel_launch(void* const* d_in, const int* in_sizes, int n_in,
                              void* d_out, int out_size) {
    const float* x   = (const float*)d_in[0];
    const void*  ei  = d_in[1];
    const float* W1  = (const float*)d_in[2];
    const float* as1 = (const float*)d_in[3];
    const float* ad1 = (const float*)d_in[4];
    const float* b1  = (const float*)d_in[5];
    const float* W2  = (const float*)d_in[6];
    const float* as2 = (const float*)d_in[7];
    const float* ad2 = (const float*)d_in[8];
    const float* b2  = (const float*)d_in[9];
    float* out = (float*)d_out;

    k_init<<<(NN + 255) / 256, 256>>>();
    k_detect<<<(NE + 255) / 256, 256>>>((const int*)ei);
    k_hist<<<(ET + 255) / 256, 256>>>(ei);
    k_scanA<<<NB, 256>>>();
    k_scanB<<<1, 256>>>();
    k_scanC<<<NB, 256>>>();
    k_scatter<<<(ET + 255) / 256, 256>>>(ei);
    k_vsd<<<1, 128>>>(W1, as1, ad1);
    k_alpha<<<(NN + 255) / 256, 256>>>(x);
    k_agg<<<(NN * NH + 255) / 256, 256>>>(x);
    k_proj<<<2048, 256>>>(W1, b1, W2, as2, ad2);
    k_layer2<<<(NN * 32 + 255) / 256, 256>>>(out, b2);
}

// round 3
// speedup vs baseline: 3.0963x; 1.3099x over previous
#include <cuda_runtime.h>

#define NN 50000
#define NE 200000
#define ET 250000   // edges + self loops
#define IC 14
#define HD 128
#define NH 8
#define OD 4
#define NS 0.2f
#define NB 196      // scan blocks = ceil(NN/256)

typedef unsigned long long ull;

// ---- scratch (static __device__ arrays; no allocations) ----
__device__ int    g_deg[NN];
__device__ int    g_rowptr[NN + 1];
__device__ int    g_cursor[NN];
__device__ int    g_col[ET];
__device__ int    g_bsum[NB];
__device__ int    g_boff[256];
__device__ float  g_as[NN * NH];
__device__ float  g_ad[NN * NH];
__device__ float  g_zT[NH * IC * NN];   // [h*IC+c][n] transposed
__device__ float4 g_h2p[2 * NN];        // partial h2 per head-half
__device__ float4 g_h2[NN];
__device__ float  g_a2s[NN];
__device__ float  g_a2d[NN];
__device__ int    g_is64 = 1;           // static init; only 0-writes at runtime

// ---- packed f32x2 helpers ----
__device__ __forceinline__ ull pk2(float lo, float hi) {
    ull r;
    asm("mov.b64 %0, {%1, %2};" : "=l"(r) : "f"(lo), "f"(hi));
    return r;
}
__device__ __forceinline__ void upk2(ull v, float& lo, float& hi) {
    asm("mov.b64 {%0, %1}, %2;" : "=f"(lo), "=f"(hi) : "l"(v));
}
__device__ __forceinline__ ull fma2(ull a, ull b, ull c) {
    ull d;
    asm("fma.rn.f32x2 %0, %1, %2, %3;" : "=l"(d) : "l"(a), "l"(b), "l"(c));
    return d;
}
__device__ __forceinline__ ull add2(ull a, ull b) {
    ull d;
    asm("add.rn.f32x2 %0, %1, %2;" : "=l"(d) : "l"(a), "l"(b));
    return d;
}

// zero degree counters + detect edge dtype (int64 iff all high words zero)
__global__ void k_pre(const int* __restrict__ p) {
    int i = blockIdx.x * blockDim.x + threadIdx.x;
    if (i < NN) g_deg[i] = 0;
    if (i < NE && p[2 * i + 1] != 0) g_is64 = 0;
}

__device__ __forceinline__ int load_edge(const void* ei, int idx, int is64) {
    if (is64) return (int)((const long long*)ei)[idx];
    return ((const int*)ei)[idx];
}

__global__ void k_hist(const void* __restrict__ ei) {
    int i = blockIdx.x * blockDim.x + threadIdx.x;
    if (i >= ET) return;
    int is64 = g_is64;
    int dst = (i < NE) ? load_edge(ei, NE + i, is64) : (i - NE);
    atomicAdd(&g_deg[dst], 1);
}

__device__ __forceinline__ int block_scan_256(int v, int t) {
    __shared__ int wt[8];
    int lane = t & 31, w = t >> 5;
    int s = v;
#pragma unroll
    for (int o = 1; o < 32; o <<= 1) {
        int u = __shfl_up_sync(0xffffffffu, s, o);
        if (lane >= o) s += u;
    }
    if (lane == 31) wt[w] = s;
    __syncthreads();
    if (t < 8) {
        int u = wt[t];
#pragma unroll
        for (int o = 1; o < 8; o <<= 1) {
            int x = __shfl_up_sync(0xffu, u, o);
            if (t >= o) u += x;
        }
        wt[t] = u;
    }
    __syncthreads();
    return s + (w > 0 ? wt[w - 1] : 0);  // inclusive
}

__global__ void k_scanA() {
    int t = threadIdx.x;
    int i = blockIdx.x * 256 + t;
    int v = (i < NN) ? g_deg[i] : 0;
    int incl = block_scan_256(v, t);
    if (i < NN) g_rowptr[i] = incl - v;
    if (t == 255) g_bsum[blockIdx.x] = incl;
}

__global__ void k_scanB() {
    int t = threadIdx.x;
    int v = (t < NB) ? g_bsum[t] : 0;
    int incl = block_scan_256(v, t);
    g_boff[t] = incl - v;
    if (t == NB - 1) g_rowptr[NN] = incl;
}

__global__ void k_scanC() {
    int i = blockIdx.x * 256 + threadIdx.x;
    if (i < NN) {
        int r = g_rowptr[i] + g_boff[blockIdx.x];
        g_rowptr[i] = r;
        g_cursor[i] = r;
    }
}

__global__ void k_scatter(const void* __restrict__ ei) {
    int i = blockIdx.x * blockDim.x + threadIdx.x;
    if (i >= ET) return;
    int is64 = g_is64;
    int src, dst;
    if (i < NE) {
        src = load_edge(ei, i, is64);
        dst = load_edge(ei, NE + i, is64);
    } else {
        src = i - NE;
        dst = i - NE;
    }
    int pos = atomicAdd(&g_cursor[dst], 1);
    g_col[pos] = src;
}

// Per-block redundant v_s/v_d compute (cheap) + per-node attention scalars.
__global__ void k_alpha(const float* __restrict__ x, const float* __restrict__ W1,
                        const float* __restrict__ as1, const float* __restrict__ ad1) {
    __shared__ float vs[IC * NH], vd[IC * NH];
    int t = threadIdx.x;
    if (t < IC * NH) {
        int c = t / NH, h = t % NH;
        float s = 0.f, d = 0.f;
        for (int f = 0; f < HD; f++) {
            float w = W1[c * (NH * HD) + h * HD + f];
            s = fmaf(w, as1[h * HD + f], s);
            d = fmaf(w, ad1[h * HD + f], d);
        }
        vs[t] = s;
        vd[t] = d;
    }
    __syncthreads();
    int n = blockIdx.x * 256 + t;
    if (n >= NN) return;
    float xr[IC];
#pragma unroll
    for (int c = 0; c < IC; c++) xr[c] = x[n * IC + c];
#pragma unroll
    for (int h = 0; h < NH; h++) {
        float s = 0.f, d = 0.f;
#pragma unroll
        for (int c = 0; c < IC; c++) {
            s = fmaf(xr[c], vs[c * NH + h], s);
            d = fmaf(xr[c], vd[c * NH + h], d);
        }
        g_as[n * NH + h] = s;
        g_ad[n * NH + h] = d;
    }
}

// Aggregation: one thread per (head, node), single pass (no max subtraction;
// softmax is shift-invariant and logits are small). Coalesced transposed z out.
__global__ void k_agg(const float* __restrict__ x) {
    int idx = blockIdx.x * blockDim.x + threadIdx.x;
    if (idx >= NN * NH) return;
    const int n = idx % NN;
    const int h = idx / NN;
    const int r0 = g_rowptr[n], r1 = g_rowptr[n + 1];
    const float adn = g_ad[n * NH + h];
    float ss = 0.f;
    float zc[IC];
#pragma unroll
    for (int c = 0; c < IC; c++) zc[c] = 0.f;
    for (int e = r0; e < r1; e++) {
        int s = g_col[e];
        float v = g_as[s * NH + h] + adn;
        v = (v >= 0.f) ? v : NS * v;
        float w = __expf(v);
        ss += w;
        const float* xp = x + s * IC;
#pragma unroll
        for (int c = 0; c < IC; c++) zc[c] = fmaf(w, __ldg(xp + c), zc[c]);
    }
    float inv = 1.f / (ss + 1e-16f);
#pragma unroll
    for (int c = 0; c < IC; c++) g_zT[(h * IC + c) * NN + n] = zc[c] * inv;
}

// Projection: lane = node. gridDim.y = head half (0: heads 0-3, 1: heads 4-7).
// Weights packed into smem (broadcast reads); per-lane h2 accumulation ->
// no shuffles/barriers in hot loop. Packed f32x2 over output pairs.
#define SW_ROW 20
__global__ void __launch_bounds__(128)
k_proj(const float* __restrict__ W1, const float* __restrict__ b1,
       const float* __restrict__ W2) {
    __shared__ ull sw[256][SW_ROW];  // 40960 B
    const int t = threadIdx.x;
    const int half = blockIdx.y;
    // fill: each thread handles 2 o-pair rows
#pragma unroll
    for (int r = 0; r < 2; r++) {
        int p = t + r * 128;
        int op = half * 256 + p;
        int o0 = 2 * op, o1 = o0 + 1;
#pragma unroll
        for (int c = 0; c < IC; c++)
            sw[p][c] = pk2(W1[c * (NH * HD) + o0], W1[c * (NH * HD) + o1]);
        sw[p][14] = pk2(b1[o0], b1[o1]);
        sw[p][15] = 0;
        sw[p][16] = pk2(W2[o0 * OD + 0], W2[o0 * OD + 1]);
        sw[p][17] = pk2(W2[o0 * OD + 2], W2[o0 * OD + 3]);
        sw[p][18] = pk2(W2[o1 * OD + 0], W2[o1 * OD + 1]);
        sw[p][19] = pk2(W2[o1 * OD + 2], W2[o1 * OD + 3]);
    }
    __syncthreads();
    const int n = blockIdx.x * 128 + t;
    if (n >= NN) return;

    ull h2a = 0, h2b = 0;
#pragma unroll
    for (int hl = 0; hl < 4; hl++) {
        const int h = half * 4 + hl;
        ull zz[IC];
#pragma unroll
        for (int c = 0; c < IC; c++) {
            float zv = g_zT[(h * IC + c) * NN + n];
            zz[c] = pk2(zv, zv);
        }
#pragma unroll 4
        for (int q = 0; q < 64; q++) {
            const int p = hl * 64 + q;
            const ulonglong2* row = (const ulonglong2*)&sw[p][0];
            ull acc0 = sw[p][14];  // b1 pair
            ull acc1 = 0;
#pragma unroll
            for (int cc = 0; cc < 7; cc++) {
                ulonglong2 w = row[cc];
                acc0 = fma2(zz[2 * cc], w.x, acc0);
                acc1 = fma2(zz[2 * cc + 1], w.y, acc1);
            }
            acc0 = add2(acc0, acc1);
            float t0, t1;
            upk2(acc0, t0, t1);
            float e0 = (t0 > 0.f) ? t0 : (__expf(t0) - 1.f);
            float e1 = (t1 > 0.f) ? t1 : (__expf(t1) - 1.f);
            ull aa0 = pk2(e0, e0), aa1 = pk2(e1, e1);
            ulonglong2 w2a = *(const ulonglong2*)&sw[p][16];
            ulonglong2 w2b = *(const ulonglong2*)&sw[p][18];
            h2a = fma2(aa0, w2a.x, h2a);
            h2b = fma2(aa0, w2a.y, h2b);
            h2a = fma2(aa1, w2b.x, h2a);
            h2b = fma2(aa1, w2b.y, h2b);
        }
    }
    float4 o4;
    upk2(h2a, o4.x, o4.y);
    upk2(h2b, o4.z, o4.w);
    g_h2p[half * NN + n] = o4;
}

// Combine head-half partials; layer-2 attention scalars.
__global__ void k_att2(const float* __restrict__ as2, const float* __restrict__ ad2) {
    int n = blockIdx.x * blockDim.x + threadIdx.x;
    if (n >= NN) return;
    float4 a = g_h2p[n], b = g_h2p[NN + n];
    float4 h;
    h.x = a.x + b.x; h.y = a.y + b.y; h.z = a.z + b.z; h.w = a.w + b.w;
    g_h2[n] = h;
    g_a2s[n] = h.x * __ldg(as2 + 0) + h.y * __ldg(as2 + 1) +
               h.z * __ldg(as2 + 2) + h.w * __ldg(as2 + 3);
    g_a2d[n] = h.x * __ldg(ad2 + 0) + h.y * __ldg(ad2 + 1) +
               h.z * __ldg(ad2 + 2) + h.w * __ldg(ad2 + 3);
}

// Layer-2: one thread per destination node, single pass.
__global__ void k_layer2(float* __restrict__ out, const float* __restrict__ b2) {
    int n = blockIdx.x * blockDim.x + threadIdx.x;
    if (n >= NN) return;
    const int r0 = g_rowptr[n], r1 = g_rowptr[n + 1];
    const float adn = g_a2d[n];
    float ss = 0.f, ax = 0.f, ay = 0.f, az = 0.f, aw = 0.f;
    for (int e = r0; e < r1; e++) {
        int s = g_col[e];
        float v = g_a2s[s] + adn;
        v = (v >= 0.f) ? v : NS * v;
        float w = __expf(v);
        ss += w;
        float4 hv = g_h2[s];
        ax = fmaf(w, hv.x, ax);
        ay = fmaf(w, hv.y, ay);
        az = fmaf(w, hv.z, az);
        aw = fmaf(w, hv.w, aw);
    }
    float inv = 1.f / (ss + 1e-16f);
    float4 o4;
    o4.x = ax * inv + __ldg(b2 + 0);
    o4.y = ay * inv + __ldg(b2 + 1);
    o4.z = az * inv + __ldg(b2 + 2);
    o4.w = aw * inv + __ldg(b2 + 3);
    ((float4*)out)[n] = o4;
}

extern "C" void kernel_launch(void* const* d_in, const int* in_sizes, int n_in,
                              void* d_out, int out_size) {
    const float* x   = (const float*)d_in[0];
    const void*  ei  = d_in[1];
    const float* W1  = (const float*)d_in[2];
    const float* as1 = (const float*)d_in[3];
    const float* ad1 = (const float*)d_in[4];
    const float* b1  = (const float*)d_in[5];
    const float* W2  = (const float*)d_in[6];
    const float* as2 = (const float*)d_in[7];
    const float* ad2 = (const float*)d_in[8];
    const float* b2  = (const float*)d_in[9];
    float* out = (float*)d_out;

    k_pre<<<(NE + 255) / 256, 256>>>((const int*)ei);
    k_hist<<<(ET + 255) / 256, 256>>>(ei);
    k_scanA<<<NB, 256>>>();
    k_scanB<<<1, 256>>>();
    k_scanC<<<NB, 256>>>();
    k_scatter<<<(ET + 255) / 256, 256>>>(ei);
    k_alpha<<<NB, 256>>>(x, W1, as1, ad1);
    k_agg<<<(NN * NH + 255) / 256, 256>>>(x);
    dim3 pg((NN + 127) / 128, 2);
    k_proj<<<pg, 128>>>(W1, b1, W2);
    k_att2<<<NB, 256>>>(as2, ad2);
    k_layer2<<<NB, 256>>>(out, b2);
}

// round 4
// speedup vs baseline: 3.9696x; 1.2820x over previous
#include <cuda_runtime.h>

#define NN 50000
#define NE 200000
#define ET 250000   // edges + self loops
#define IC 14
#define HD 128
#define NH 8
#define OD 4
#define NS 0.2f
#define NB 196      // per-node blocks = ceil(NN/256)

typedef unsigned long long ull;

// ---- scratch (static __device__ arrays; no allocations) ----
__device__ int    g_deg[NN];
__device__ int    g_rowptr[NN + 1];
__device__ int    g_cursor[NN];
__device__ int    g_col[ET];
__device__ int    g_bsum[NB];
__device__ int    g_boff[256];
__device__ int    g_tick;
__device__ float4 g_as4[2 * NN];        // [half][n]: att-src for heads 4h..4h+3
__device__ float4 g_ad4[2 * NN];
__device__ float4 g_x16[NN * 4];        // x rows padded 14 -> 16 floats
__device__ float  g_zT[NH * IC * NN];   // [h*IC+c][n]
__device__ float4 g_h2p[2 * NN];        // h2 partials per head-half
__device__ int    g_is64 = 1;

// ---- packed f32x2 helpers ----
__device__ __forceinline__ ull pk2(float lo, float hi) {
    ull r;
    asm("mov.b64 %0, {%1, %2};" : "=l"(r) : "f"(lo), "f"(hi));
    return r;
}
__device__ __forceinline__ void upk2(ull v, float& lo, float& hi) {
    asm("mov.b64 {%0, %1}, %2;" : "=f"(lo), "=f"(hi) : "l"(v));
}
__device__ __forceinline__ ull fma2(ull a, ull b, ull c) {
    ull d;
    asm("fma.rn.f32x2 %0, %1, %2, %3;" : "=l"(d) : "l"(a), "l"(b), "l"(c));
    return d;
}
__device__ __forceinline__ ull add2(ull a, ull b) {
    ull d;
    asm("add.rn.f32x2 %0, %1, %2;" : "=l"(d) : "l"(a), "l"(b));
    return d;
}
__device__ __forceinline__ float lrelu(float v) {
    return (v >= 0.f) ? v : NS * v;
}

// zero deg + reset ticket + detect edge dtype
__global__ void k_pre(const int* __restrict__ p) {
    int i = blockIdx.x * blockDim.x + threadIdx.x;
    if (i < NN) g_deg[i] = 0;
    if (i == 0) g_tick = 0;
    if (i < NE && p[2 * i + 1] != 0) g_is64 = 0;
}

__device__ __forceinline__ int load_edge(const void* ei, int idx, int is64) {
    if (is64) return (int)((const long long*)ei)[idx];
    return ((const int*)ei)[idx];
}

__global__ void k_hist(const void* __restrict__ ei) {
    int i = blockIdx.x * blockDim.x + threadIdx.x;
    if (i >= ET) return;
    int is64 = g_is64;
    int dst = (i < NE) ? load_edge(ei, NE + i, is64) : (i - NE);
    atomicAdd(&g_deg[dst], 1);
}

__device__ __forceinline__ int block_scan_256(int v, int t) {
    __shared__ int wt[8];
    int lane = t & 31, w = t >> 5;
    int s = v;
#pragma unroll
    for (int o = 1; o < 32; o <<= 1) {
        int u = __shfl_up_sync(0xffffffffu, s, o);
        if (lane >= o) s += u;
    }
    if (lane == 31) wt[w] = s;
    __syncthreads();
    if (t < 8) {
        int u = wt[t];
#pragma unroll
        for (int o = 1; o < 8; o <<= 1) {
            int x = __shfl_up_sync(0xffu, u, o);
            if (t >= o) u += x;
        }
        wt[t] = u;
    }
    __syncthreads();
    return s + (w > 0 ? wt[w - 1] : 0);  // inclusive
}

// block-local exclusive scan + last-finishing block scans the block sums
__global__ void k_scanAB() {
    __shared__ int lastsh;
    int t = threadIdx.x;
    int i = blockIdx.x * 256 + t;
    int v = (i < NN) ? g_deg[i] : 0;
    int incl = block_scan_256(v, t);
    if (i < NN) g_rowptr[i] = incl - v;
    if (t == 255) g_bsum[blockIdx.x] = incl;
    __threadfence();
    __syncthreads();
    if (t == 0) lastsh = (atomicAdd(&g_tick, 1) == NB - 1);
    __syncthreads();
    if (lastsh) {
        __threadfence();
        int u = (t < NB) ? *((volatile int*)&g_bsum[t]) : 0;
        int incl2 = block_scan_256(u, t);
        if (t < NB) g_boff[t] = incl2 - u;
        if (t == NB - 1) g_rowptr[NN] = incl2;
    }
}

// scanC fixup + cursor init + attention scalars + padded x copy
__global__ void k_alphaC(const float* __restrict__ x, const float* __restrict__ W1,
                         const float* __restrict__ as1, const float* __restrict__ ad1) {
    __shared__ float vs[IC * NH], vd[IC * NH];
    int t = threadIdx.x;
    if (t < IC * NH) {
        int c = t / NH, h = t % NH;
        float s = 0.f, d = 0.f;
        for (int f = 0; f < HD; f++) {
            float w = W1[c * (NH * HD) + h * HD + f];
            s = fmaf(w, as1[h * HD + f], s);
            d = fmaf(w, ad1[h * HD + f], d);
        }
        vs[t] = s;
        vd[t] = d;
    }
    __syncthreads();
    int n = blockIdx.x * 256 + t;
    if (n >= NN) return;
    int r = g_rowptr[n] + g_boff[blockIdx.x];
    g_rowptr[n] = r;
    g_cursor[n] = r;
    float xr[IC];
#pragma unroll
    for (int c = 0; c < IC; c++) xr[c] = x[n * IC + c];
    float4 xv;
    xv.x = xr[0]; xv.y = xr[1]; xv.z = xr[2]; xv.w = xr[3];
    g_x16[4 * n + 0] = xv;
    xv.x = xr[4]; xv.y = xr[5]; xv.z = xr[6]; xv.w = xr[7];
    g_x16[4 * n + 1] = xv;
    xv.x = xr[8]; xv.y = xr[9]; xv.z = xr[10]; xv.w = xr[11];
    g_x16[4 * n + 2] = xv;
    xv.x = xr[12]; xv.y = xr[13]; xv.z = 0.f; xv.w = 0.f;
    g_x16[4 * n + 3] = xv;
    float a[NH], d[NH];
#pragma unroll
    for (int h = 0; h < NH; h++) {
        float s = 0.f, dd = 0.f;
#pragma unroll
        for (int c = 0; c < IC; c++) {
            s = fmaf(xr[c], vs[c * NH + h], s);
            dd = fmaf(xr[c], vd[c * NH + h], dd);
        }
        a[h] = s;
        d[h] = dd;
    }
    g_as4[n] = make_float4(a[0], a[1], a[2], a[3]);
    g_as4[NN + n] = make_float4(a[4], a[5], a[6], a[7]);
    g_ad4[n] = make_float4(d[0], d[1], d[2], d[3]);
    g_ad4[NN + n] = make_float4(d[4], d[5], d[6], d[7]);
}

__global__ void k_scatter(const void* __restrict__ ei) {
    int i = blockIdx.x * blockDim.x + threadIdx.x;
    if (i >= ET) return;
    int is64 = g_is64;
    int src, dst;
    if (i < NE) {
        src = load_edge(ei, i, is64);
        dst = load_edge(ei, NE + i, is64);
    } else {
        src = i - NE;
        dst = i - NE;
    }
    int pos = atomicAdd(&g_cursor[dst], 1);
    g_col[pos] = src;
}

// Aggregation: thread = node, 4 heads per thread (blockIdx.y = head half).
// Single softmax pass (shift-invariance; logits are O(1)). Coalesced zT out.
__global__ void __launch_bounds__(256) k_agg() {
    int t = threadIdx.x;
    int n = blockIdx.x * 256 + t;
    if (n >= NN) return;
    const int half = blockIdx.y;
    const float4 adn = g_ad4[half * NN + n];
    const int r0 = g_rowptr[n], r1 = g_rowptr[n + 1];
    float ss0 = 0.f, ss1 = 0.f, ss2 = 0.f, ss3 = 0.f;
    float zc[4][IC];
#pragma unroll
    for (int j = 0; j < 4; j++)
#pragma unroll
        for (int c = 0; c < IC; c++) zc[j][c] = 0.f;
    for (int e = r0; e < r1; e++) {
        int s = g_col[e];
        float4 a4 = g_as4[half * NN + s];
        float w0 = __expf(lrelu(a4.x + adn.x));
        float w1 = __expf(lrelu(a4.y + adn.y));
        float w2 = __expf(lrelu(a4.z + adn.z));
        float w3 = __expf(lrelu(a4.w + adn.w));
        ss0 += w0; ss1 += w1; ss2 += w2; ss3 += w3;
        float4 xa = g_x16[4 * s + 0];
        float4 xb = g_x16[4 * s + 1];
        float4 xc = g_x16[4 * s + 2];
        float4 xd = g_x16[4 * s + 3];
        float xr[IC] = {xa.x, xa.y, xa.z, xa.w, xb.x, xb.y, xb.z, xb.w,
                        xc.x, xc.y, xc.z, xc.w, xd.x, xd.y};
#pragma unroll
        for (int c = 0; c < IC; c++) {
            zc[0][c] = fmaf(w0, xr[c], zc[0][c]);
            zc[1][c] = fmaf(w1, xr[c], zc[1][c]);
            zc[2][c] = fmaf(w2, xr[c], zc[2][c]);
            zc[3][c] = fmaf(w3, xr[c], zc[3][c]);
        }
    }
    float inv[4];
    inv[0] = 1.f / (ss0 + 1e-16f);
    inv[1] = 1.f / (ss1 + 1e-16f);
    inv[2] = 1.f / (ss2 + 1e-16f);
    inv[3] = 1.f / (ss3 + 1e-16f);
#pragma unroll
    for (int j = 0; j < 4; j++) {
        const int h = half * 4 + j;
#pragma unroll
        for (int c = 0; c < IC; c++)
            g_zT[(h * IC + c) * NN + n] = zc[j][c] * inv[j];
    }
}

// Projection: lane = node; blockIdx.y = head half. Weights in smem, packed
// f32x2, per-lane h2 accumulation (no shuffles/barriers in hot loop).
#define SW_ROW 20
__global__ void __launch_bounds__(128)
k_proj(const float* __restrict__ W1, const float* __restrict__ b1,
       const float* __restrict__ W2) {
    __shared__ ull sw[256][SW_ROW];  // 40960 B
    const int t = threadIdx.x;
    const int half = blockIdx.y;
#pragma unroll
    for (int r = 0; r < 2; r++) {
        int p = t + r * 128;
        int op = half * 256 + p;
        int o0 = 2 * op, o1 = o0 + 1;
#pragma unroll
        for (int c = 0; c < IC; c++)
            sw[p][c] = pk2(W1[c * (NH * HD) + o0], W1[c * (NH * HD) + o1]);
        sw[p][14] = pk2(b1[o0], b1[o1]);
        sw[p][15] = 0;
        sw[p][16] = pk2(W2[o0 * OD + 0], W2[o0 * OD + 1]);
        sw[p][17] = pk2(W2[o0 * OD + 2], W2[o0 * OD + 3]);
        sw[p][18] = pk2(W2[o1 * OD + 0], W2[o1 * OD + 1]);
        sw[p][19] = pk2(W2[o1 * OD + 2], W2[o1 * OD + 3]);
    }
    __syncthreads();
    const int n = blockIdx.x * 128 + t;
    if (n >= NN) return;

    ull h2a = 0, h2b = 0;
#pragma unroll
    for (int hl = 0; hl < 4; hl++) {
        const int h = half * 4 + hl;
        ull zz[IC];
#pragma unroll
        for (int c = 0; c < IC; c++) {
            float zv = g_zT[(h * IC + c) * NN + n];
            zz[c] = pk2(zv, zv);
        }
#pragma unroll 4
        for (int q = 0; q < 64; q++) {
            const int p = hl * 64 + q;
            const ulonglong2* row = (const ulonglong2*)&sw[p][0];
            ull acc0 = sw[p][14];
            ull acc1 = 0;
#pragma unroll
            for (int cc = 0; cc < 7; cc++) {
                ulonglong2 w = row[cc];
                acc0 = fma2(zz[2 * cc], w.x, acc0);
                acc1 = fma2(zz[2 * cc + 1], w.y, acc1);
            }
            acc0 = add2(acc0, acc1);
            float t0, t1;
            upk2(acc0, t0, t1);
            float e0 = (t0 > 0.f) ? t0 : (__expf(t0) - 1.f);
            float e1 = (t1 > 0.f) ? t1 : (__expf(t1) - 1.f);
            ull aa0 = pk2(e0, e0), aa1 = pk2(e1, e1);
            ulonglong2 w2a = *(const ulonglong2*)&sw[p][16];
            ulonglong2 w2b = *(const ulonglong2*)&sw[p][18];
            h2a = fma2(aa0, w2a.x, h2a);
            h2b = fma2(aa0, w2a.y, h2b);
            h2a = fma2(aa1, w2b.x, h2a);
            h2b = fma2(aa1, w2b.y, h2b);
        }
    }
    float4 o4;
    upk2(h2a, o4.x, o4.y);
    upk2(h2b, o4.z, o4.w);
    g_h2p[half * NN + n] = o4;
}

// Layer-2: thread = destination node. Combines head-half h2 partials and
// computes a2 scalars on the fly (deletes the separate combine kernel).
__global__ void k_layer2(float* __restrict__ out, const float* __restrict__ b2,
                         const float* __restrict__ as2, const float* __restrict__ ad2) {
    int n = blockIdx.x * blockDim.x + threadIdx.x;
    if (n >= NN) return;
    const float s0 = __ldg(as2 + 0), s1 = __ldg(as2 + 1),
                s2 = __ldg(as2 + 2), s3 = __ldg(as2 + 3);
    float4 pa = g_h2p[n], pb = g_h2p[NN + n];
    float hx = pa.x + pb.x, hy = pa.y + pb.y, hz = pa.z + pb.z, hw = pa.w + pb.w;
    const float adn = hx * __ldg(ad2 + 0) + hy * __ldg(ad2 + 1) +
                      hz * __ldg(ad2 + 2) + hw * __ldg(ad2 + 3);
    const int r0 = g_rowptr[n], r1 = g_rowptr[n + 1];
    float ss = 0.f, ax = 0.f, ay = 0.f, az = 0.f, aw = 0.f;
    for (int e = r0; e < r1; e++) {
        int s = g_col[e];
        float4 qa = g_h2p[s], qb = g_h2p[NN + s];
        float vx = qa.x + qb.x, vy = qa.y + qb.y,
              vz = qa.z + qb.z, vw = qa.w + qb.w;
        float v = vx * s0 + vy * s1 + vz * s2 + vw * s3 + adn;
        v = lrelu(v);
        float w = __expf(v);
        ss += w;
        ax = fmaf(w, vx, ax);
        ay = fmaf(w, vy, ay);
        az = fmaf(w, vz, az);
        aw = fmaf(w, vw, aw);
    }
    float inv = 1.f / (ss + 1e-16f);
    float4 o4;
    o4.x = ax * inv + __ldg(b2 + 0);
    o4.y = ay * inv + __ldg(b2 + 1);
    o4.z = az * inv + __ldg(b2 + 2);
    o4.w = aw * inv + __ldg(b2 + 3);
    ((float4*)out)[n] = o4;
}

extern "C" void kernel_launch(void* const* d_in, const int* in_sizes, int n_in,
                              void* d_out, int out_size) {
    const float* x   = (const float*)d_in[0];
    const void*  ei  = d_in[1];
    const float* W1  = (const float*)d_in[2];
    const float* as1 = (const float*)d_in[3];
    const float* ad1 = (const float*)d_in[4];
    const float* b1  = (const float*)d_in[5];
    const float* W2  = (const float*)d_in[6];
    const float* as2 = (const float*)d_in[7];
    const float* ad2 = (const float*)d_in[8];
    const float* b2  = (const float*)d_in[9];
    float* out = (float*)d_out;

    k_pre<<<(NE + 255) / 256, 256>>>((const int*)ei);
    k_hist<<<(ET + 255) / 256, 256>>>(ei);
    k_scanAB<<<NB, 256>>>();
    k_alphaC<<<NB, 256>>>(x, W1, as1, ad1);
    k_scatter<<<(ET + 255) / 256, 256>>>(ei);
    dim3 ag(NB, 2);
    k_agg<<<ag, 256>>>();
    dim3 pg((NN + 127) / 128, 2);
    k_proj<<<pg, 128>>>(W1, b1, W2);
    k_layer2<<<NB, 256>>>(out, b2, as2, ad2);
}

// round 5
// speedup vs baseline: 4.2308x; 1.0658x over previous
#include <cuda_runtime.h>

#define NN 50000
#define NE 200000
#define ET 250000   // edges + self loops
#define IC 14
#define HD 128
#define NH 8
#define OD 4
#define NS 0.2f
#define NB 196      // per-node blocks = ceil(NN/256)

typedef unsigned long long ull;

// ---- scratch (static __device__ arrays; no allocations) ----
__device__ int    g_deg[NN];
__device__ int    g_rowptr[NN + 1];
__device__ int    g_cursor[NN];
__device__ int    g_col[ET];
__device__ int    g_bsum[NB];
__device__ int    g_boff[256];
__device__ int    g_tick;
__device__ float  g_vs[IC * NH];
__device__ float  g_vd[IC * NH];
__device__ float4 g_as4[2 * NN];        // [half][n]: att-src for heads 4h..4h+3
__device__ float4 g_ad4[2 * NN];
__device__ float4 g_x16[NN * 4];        // x rows padded 14 -> 16 floats
__device__ float  g_zT[NH * IC * NN];   // [h*IC+c][n]
__device__ float4 g_h2p[2 * NN];        // h2 partials per head-half
__device__ int    g_is64 = 1;

// ---- packed f32x2 helpers ----
__device__ __forceinline__ ull pk2(float lo, float hi) {
    ull r;
    asm("mov.b64 %0, {%1, %2};" : "=l"(r) : "f"(lo), "f"(hi));
    return r;
}
__device__ __forceinline__ void upk2(ull v, float& lo, float& hi) {
    asm("mov.b64 {%0, %1}, %2;" : "=f"(lo), "=f"(hi) : "l"(v));
}
__device__ __forceinline__ ull fma2(ull a, ull b, ull c) {
    ull d;
    asm("fma.rn.f32x2 %0, %1, %2, %3;" : "=l"(d) : "l"(a), "l"(b), "l"(c));
    return d;
}
__device__ __forceinline__ ull add2(ull a, ull b) {
    ull d;
    asm("add.rn.f32x2 %0, %1, %2;" : "=l"(d) : "l"(a), "l"(b));
    return d;
}
__device__ __forceinline__ float lrelu(float v) {
    return (v >= 0.f) ? v : NS * v;
}

// zero deg + reset ticket + detect edge dtype + (block 0) v_s/v_d precompute
__global__ void k_pre(const int* __restrict__ p, const float* __restrict__ W1,
                      const float* __restrict__ as1, const float* __restrict__ ad1) {
    int t = threadIdx.x;
    int i = blockIdx.x * blockDim.x + t;
    if (i < NN) g_deg[i] = 0;
    if (i == 0) g_tick = 0;
    if (i < NE && p[2 * i + 1] != 0) g_is64 = 0;
    if (blockIdx.x == 0 && t < IC * NH) {
        int c = t / NH, h = t % NH;
        float s = 0.f, d = 0.f;
        for (int f = 0; f < HD; f++) {
            float w = W1[c * (NH * HD) + h * HD + f];
            s = fmaf(w, as1[h * HD + f], s);
            d = fmaf(w, ad1[h * HD + f], d);
        }
        g_vs[t] = s;
        g_vd[t] = d;
    }
}

__device__ __forceinline__ int load_edge(const void* ei, int idx, int is64) {
    if (is64) return (int)((const long long*)ei)[idx];
    return ((const int*)ei)[idx];
}

__global__ void k_hist(const void* __restrict__ ei) {
    int i = blockIdx.x * blockDim.x + threadIdx.x;
    if (i >= ET) return;
    int is64 = g_is64;
    int dst = (i < NE) ? load_edge(ei, NE + i, is64) : (i - NE);
    atomicAdd(&g_deg[dst], 1);
}

__device__ __forceinline__ int block_scan_256(int v, int t) {
    __shared__ int wt[8];
    int lane = t & 31, w = t >> 5;
    int s = v;
#pragma unroll
    for (int o = 1; o < 32; o <<= 1) {
        int u = __shfl_up_sync(0xffffffffu, s, o);
        if (lane >= o) s += u;
    }
    if (lane == 31) wt[w] = s;
    __syncthreads();
    if (t < 8) {
        int u = wt[t];
#pragma unroll
        for (int o = 1; o < 8; o <<= 1) {
            int x = __shfl_up_sync(0xffu, u, o);
            if (t >= o) u += x;
        }
        wt[t] = u;
    }
    __syncthreads();
    return s + (w > 0 ? wt[w - 1] : 0);  // inclusive
}

// block-local exclusive scan + last-finishing block scans the block sums
__global__ void k_scanAB() {
    __shared__ int lastsh;
    int t = threadIdx.x;
    int i = blockIdx.x * 256 + t;
    int v = (i < NN) ? g_deg[i] : 0;
    int incl = block_scan_256(v, t);
    if (i < NN) g_rowptr[i] = incl - v;
    if (t == 255) g_bsum[blockIdx.x] = incl;
    __threadfence();
    __syncthreads();
    if (t == 0) lastsh = (atomicAdd(&g_tick, 1) == NB - 1);
    __syncthreads();
    if (lastsh) {
        __threadfence();
        int u = (t < NB) ? *((volatile int*)&g_bsum[t]) : 0;
        int incl2 = block_scan_256(u, t);
        if (t < NB) g_boff[t] = incl2 - u;
        if (t == NB - 1) g_rowptr[NN] = incl2;
    }
}

// scan fixup + cursor init + attention scalars + padded x copy
// (v_s/v_d already computed once by k_pre block 0 -> cheap smem load here)
__global__ void k_alphaC(const float* __restrict__ x) {
    __shared__ float vs[IC * NH], vd[IC * NH];
    int t = threadIdx.x;
    if (t < IC * NH) {
        vs[t] = g_vs[t];
        vd[t] = g_vd[t];
    }
    __syncthreads();
    int n = blockIdx.x * 256 + t;
    if (n >= NN) return;
    int r = g_rowptr[n] + g_boff[blockIdx.x];
    g_rowptr[n] = r;
    g_cursor[n] = r;
    float xr[IC];
#pragma unroll
    for (int c = 0; c < IC; c++) xr[c] = x[n * IC + c];
    float4 xv;
    xv.x = xr[0]; xv.y = xr[1]; xv.z = xr[2]; xv.w = xr[3];
    g_x16[4 * n + 0] = xv;
    xv.x = xr[4]; xv.y = xr[5]; xv.z = xr[6]; xv.w = xr[7];
    g_x16[4 * n + 1] = xv;
    xv.x = xr[8]; xv.y = xr[9]; xv.z = xr[10]; xv.w = xr[11];
    g_x16[4 * n + 2] = xv;
    xv.x = xr[12]; xv.y = xr[13]; xv.z = 0.f; xv.w = 0.f;
    g_x16[4 * n + 3] = xv;
    float a[NH], d[NH];
#pragma unroll
    for (int h = 0; h < NH; h++) {
        float s = 0.f, dd = 0.f;
#pragma unroll
        for (int c = 0; c < IC; c++) {
            s = fmaf(xr[c], vs[c * NH + h], s);
            dd = fmaf(xr[c], vd[c * NH + h], dd);
        }
        a[h] = s;
        d[h] = dd;
    }
    g_as4[n] = make_float4(a[0], a[1], a[2], a[3]);
    g_as4[NN + n] = make_float4(a[4], a[5], a[6], a[7]);
    g_ad4[n] = make_float4(d[0], d[1], d[2], d[3]);
    g_ad4[NN + n] = make_float4(d[4], d[5], d[6], d[7]);
}

__global__ void k_scatter(const void* __restrict__ ei) {
    int i = blockIdx.x * blockDim.x + threadIdx.x;
    if (i >= ET) return;
    int is64 = g_is64;
    int src, dst;
    if (i < NE) {
        src = load_edge(ei, i, is64);
        dst = load_edge(ei, NE + i, is64);
    } else {
        src = i - NE;
        dst = i - NE;
    }
    int pos = atomicAdd(&g_cursor[dst], 1);
    g_col[pos] = src;
}

// Aggregation: thread = node, 4 heads per thread (blockIdx.y = head half).
// Single softmax pass (shift-invariance; logits are O(1)). Coalesced zT out.
__global__ void __launch_bounds__(256) k_agg() {
    int t = threadIdx.x;
    int n = blockIdx.x * 256 + t;
    if (n >= NN) return;
    const int half = blockIdx.y;
    const float4 adn = g_ad4[half * NN + n];
    const int r0 = g_rowptr[n], r1 = g_rowptr[n + 1];
    float ss0 = 0.f, ss1 = 0.f, ss2 = 0.f, ss3 = 0.f;
    float zc[4][IC];
#pragma unroll
    for (int j = 0; j < 4; j++)
#pragma unroll
        for (int c = 0; c < IC; c++) zc[j][c] = 0.f;
    for (int e = r0; e < r1; e++) {
        int s = g_col[e];
        float4 a4 = g_as4[half * NN + s];
        float w0 = __expf(lrelu(a4.x + adn.x));
        float w1 = __expf(lrelu(a4.y + adn.y));
        float w2 = __expf(lrelu(a4.z + adn.z));
        float w3 = __expf(lrelu(a4.w + adn.w));
        ss0 += w0; ss1 += w1; ss2 += w2; ss3 += w3;
        float4 xa = g_x16[4 * s + 0];
        float4 xb = g_x16[4 * s + 1];
        float4 xc = g_x16[4 * s + 2];
        float4 xd = g_x16[4 * s + 3];
        float xr[IC] = {xa.x, xa.y, xa.z, xa.w, xb.x, xb.y, xb.z, xb.w,
                        xc.x, xc.y, xc.z, xc.w, xd.x, xd.y};
#pragma unroll
        for (int c = 0; c < IC; c++) {
            zc[0][c] = fmaf(w0, xr[c], zc[0][c]);
            zc[1][c] = fmaf(w1, xr[c], zc[1][c]);
            zc[2][c] = fmaf(w2, xr[c], zc[2][c]);
            zc[3][c] = fmaf(w3, xr[c], zc[3][c]);
        }
    }
    float inv[4];
    inv[0] = 1.f / (ss0 + 1e-16f);
    inv[1] = 1.f / (ss1 + 1e-16f);
    inv[2] = 1.f / (ss2 + 1e-16f);
    inv[3] = 1.f / (ss3 + 1e-16f);
#pragma unroll
    for (int j = 0; j < 4; j++) {
        const int h = half * 4 + j;
#pragma unroll
        for (int c = 0; c < IC; c++)
            g_zT[(h * IC + c) * NN + n] = zc[j][c] * inv[j];
    }
}

// Projection: lane = node; blockIdx.y = head half. Weights in smem, packed
// f32x2, per-lane h2 accumulation (no shuffles/barriers in hot loop).
#define SW_ROW 20
__global__ void __launch_bounds__(128)
k_proj(const float* __restrict__ W1, const float* __restrict__ b1,
       const float* __restrict__ W2) {
    __shared__ ull sw[256][SW_ROW];  // 40960 B
    const int t = threadIdx.x;
    const int half = blockIdx.y;
#pragma unroll
    for (int r = 0; r < 2; r++) {
        int p = t + r * 128;
        int op = half * 256 + p;
        int o0 = 2 * op, o1 = o0 + 1;
#pragma unroll
        for (int c = 0; c < IC; c++)
            sw[p][c] = pk2(W1[c * (NH * HD) + o0], W1[c * (NH * HD) + o1]);
        sw[p][14] = pk2(b1[o0], b1[o1]);
        sw[p][15] = 0;
        sw[p][16] = pk2(W2[o0 * OD + 0], W2[o0 * OD + 1]);
        sw[p][17] = pk2(W2[o0 * OD + 2], W2[o0 * OD + 3]);
        sw[p][18] = pk2(W2[o1 * OD + 0], W2[o1 * OD + 1]);
        sw[p][19] = pk2(W2[o1 * OD + 2], W2[o1 * OD + 3]);
    }
    __syncthreads();
    const int n = blockIdx.x * 128 + t;
    if (n >= NN) return;

    ull h2a = 0, h2b = 0;
#pragma unroll
    for (int hl = 0; hl < 4; hl++) {
        const int h = half * 4 + hl;
        ull zz[IC];
#pragma unroll
        for (int c = 0; c < IC; c++) {
            float zv = g_zT[(h * IC + c) * NN + n];
            zz[c] = pk2(zv, zv);
        }
#pragma unroll 4
        for (int q = 0; q < 64; q++) {
            const int p = hl * 64 + q;
            const ulonglong2* row = (const ulonglong2*)&sw[p][0];
            ull acc0 = sw[p][14];
            ull acc1 = 0;
#pragma unroll
            for (int cc = 0; cc < 7; cc++) {
                ulonglong2 w = row[cc];
                acc0 = fma2(zz[2 * cc], w.x, acc0);
                acc1 = fma2(zz[2 * cc + 1], w.y, acc1);
            }
            acc0 = add2(acc0, acc1);
            float t0, t1;
            upk2(acc0, t0, t1);
            float e0 = (t0 > 0.f) ? t0 : (__expf(t0) - 1.f);
            float e1 = (t1 > 0.f) ? t1 : (__expf(t1) - 1.f);
            ull aa0 = pk2(e0, e0), aa1 = pk2(e1, e1);
            ulonglong2 w2a = *(const ulonglong2*)&sw[p][16];
            ulonglong2 w2b = *(const ulonglong2*)&sw[p][18];
            h2a = fma2(aa0, w2a.x, h2a);
            h2b = fma2(aa0, w2a.y, h2b);
            h2a = fma2(aa1, w2b.x, h2a);
            h2b = fma2(aa1, w2b.y, h2b);
        }
    }
    float4 o4;
    upk2(h2a, o4.x, o4.y);
    upk2(h2b, o4.z, o4.w);
    g_h2p[half * NN + n] = o4;
}

// Layer-2: thread = destination node. Combines head-half h2 partials and
// computes a2 scalars on the fly.
__global__ void k_layer2(float* __restrict__ out, const float* __restrict__ b2,
                         const float* __restrict__ as2, const float* __restrict__ ad2) {
    int n = blockIdx.x * blockDim.x + threadIdx.x;
    if (n >= NN) return;
    const float s0 = __ldg(as2 + 0), s1 = __ldg(as2 + 1),
                s2 = __ldg(as2 + 2), s3 = __ldg(as2 + 3);
    float4 pa = g_h2p[n], pb = g_h2p[NN + n];
    float hx = pa.x + pb.x, hy = pa.y + pb.y, hz = pa.z + pb.z, hw = pa.w + pb.w;
    const float adn = hx * __ldg(ad2 + 0) + hy * __ldg(ad2 + 1) +
                      hz * __ldg(ad2 + 2) + hw * __ldg(ad2 + 3);
    const int r0 = g_rowptr[n], r1 = g_rowptr[n + 1];
    float ss = 0.f, ax = 0.f, ay = 0.f, az = 0.f, aw = 0.f;
    for (int e = r0; e < r1; e++) {
        int s = g_col[e];
        float4 qa = g_h2p[s], qb = g_h2p[NN + s];
        float vx = qa.x + qb.x, vy = qa.y + qb.y,
              vz = qa.z + qb.z, vw = qa.w + qb.w;
        float v = vx * s0 + vy * s1 + vz * s2 + vw * s3 + adn;
        v = lrelu(v);
        float w = __expf(v);
        ss += w;
        ax = fmaf(w, vx, ax);
        ay = fmaf(w, vy, ay);
        az = fmaf(w, vz, az);
        aw = fmaf(w, vw, aw);
    }
    float inv = 1.f / (ss + 1e-16f);
    float4 o4;
    o4.x = ax * inv + __ldg(b2 + 0);
    o4.y = ay * inv + __ldg(b2 + 1);
    o4.z = az * inv + __ldg(b2 + 2);
    o4.w = aw * inv + __ldg(b2 + 3);
    ((float4*)out)[n] = o4;
}

extern "C" void kernel_launch(void* const* d_in, const int* in_sizes, int n_in,
                              void* d_out, int out_size) {
    const float* x   = (const float*)d_in[0];
    const void*  ei  = d_in[1];
    const float* W1  = (const float*)d_in[2];
    const float* as1 = (const float*)d_in[3];
    const float* ad1 = (const float*)d_in[4];
    const float* b1  = (const float*)d_in[5];
    const float* W2  = (const float*)d_in[6];
    const float* as2 = (const float*)d_in[7];
    const float* ad2 = (const float*)d_in[8];
    const float* b2  = (const float*)d_in[9];
    float* out = (float*)d_out;

    k_pre<<<(NE + 255) / 256, 256>>>((const int*)ei, W1, as1, ad1);
    k_hist<<<(ET + 255) / 256, 256>>>(ei);
    k_scanAB<<<NB, 256>>>();
    k_alphaC<<<NB, 256>>>(x);
    k_scatter<<<(ET + 255) / 256, 256>>>(ei);
    dim3 ag(NB, 2);
    k_agg<<<ag, 256>>>();
    dim3 pg((NN + 127) / 128, 2);
    k_proj<<<pg, 128>>>(W1, b1, W2);
    k_layer2<<<NB, 256>>>(out, b2, as2, ad2);
}

// round 6
// speedup vs baseline: 4.2773x; 1.0110x over previous
#include <cuda_runtime.h>

#define NN 50000
#define NE 200000
#define ET 250000   // edges + self loops
#define IC 14
#define HD 128
#define NH 8
#define OD 4
#define NS 0.2f
#define NB 196      // per-node blocks = ceil(NN/256)
#define HB 489      // hist blocks  = ceil(ET/512)

typedef unsigned long long ull;

// ---- scratch (static __device__ arrays; zero-initialized at load) ----
__device__ int    g_deg[NN];            // self-cleaned by k_scanAB each run
__device__ int    g_rowptr[NN + 1];
__device__ int    g_cursor[NN];
__device__ int    g_col[ET];
__device__ int    g_bsum[NB];
__device__ int    g_boff[256];
__device__ int    g_tick;               // epoch tickets: monotonic, never reset
__device__ int    g_ta;
__device__ int    g_tb;
__device__ float  g_vs[IC * NH];
__device__ float  g_vd[IC * NH];
__device__ float4 g_as4[2 * NN];        // [half][n]: att-src heads 4h..4h+3
__device__ float4 g_ad4[2 * NN];
__device__ float4 g_x16[NN * 4];        // x rows padded 14 -> 16 floats
__device__ float  g_zT[NH * IC * NN];   // [h*IC+c][n]
__device__ float4 g_h2p[2 * NN];        // h2 partials per head-half
__device__ int    g_is64 = 1;

// ---- packed f32x2 helpers ----
__device__ __forceinline__ ull pk2(float lo, float hi) {
    ull r;
    asm("mov.b64 %0, {%1, %2};" : "=l"(r) : "f"(lo), "f"(hi));
    return r;
}
__device__ __forceinline__ void upk2(ull v, float& lo, float& hi) {
    asm("mov.b64 {%0, %1}, %2;" : "=f"(lo), "=f"(hi) : "l"(v));
}
__device__ __forceinline__ ull fma2(ull a, ull b, ull c) {
    ull d;
    asm("fma.rn.f32x2 %0, %1, %2, %3;" : "=l"(d) : "l"(a), "l"(b), "l"(c));
    return d;
}
__device__ __forceinline__ ull add2(ull a, ull b) {
    ull d;
    asm("add.rn.f32x2 %0, %1, %2;" : "=l"(d) : "l"(a), "l"(b));
    return d;
}
__device__ __forceinline__ float lrelu(float v) {
    return (v >= 0.f) ? v : NS * v;
}

// all-resident grid barrier; epoch trick (monotonic counter, graph-replay safe)
__device__ __forceinline__ void grid_bar(int* cnt, int nb) {
    __threadfence();
    __syncthreads();
    if (threadIdx.x == 0) {
        int my = atomicAdd(cnt, 1);
        int target = (my / nb + 1) * nb;
        while (*((volatile int*)cnt) < target) {}
    }
    __syncthreads();
    __threadfence();
}

__device__ __forceinline__ int load_edge(const void* ei, int idx, int is64) {
    if (is64) return (int)((const long long*)ei)[idx];
    return ((const int*)ei)[idx];
}

// Fused: dtype detect + (block 0) v_s/v_d precompute | grid barrier | histogram.
// 489 blocks of 256 (<=4 needed per SM, capacity >=8) -> all resident, no deadlock.
__global__ void __launch_bounds__(256, 8)
k_histF(const void* __restrict__ ei, const float* __restrict__ W1,
        const float* __restrict__ as1, const float* __restrict__ ad1) {
    __shared__ float sv[224], sd[224];
    const int t = threadIdx.x;
    const int bx = blockIdx.x;
    const int base = bx * 256 + t;
    const int* p = (const int*)ei;
    // phase 1: detect (covers all NE edges with 2 strided picks)
#pragma unroll
    for (int k = 0; k < 2; k++) {
        int i = base + k * (HB * 256);
        if (i < NE && p[2 * i + 1] != 0) g_is64 = 0;
    }
    // block 0: v_s[c][h] = sum_f W1[c,h*HD+f]*as1[h,f] (2 threads per output)
    if (bx == 0) {
        if (t < 224) {
            int pp = t >> 1, part = t & 1;
            int c = pp / NH, h = pp % NH;
            float s = 0.f, d = 0.f;
            for (int f = part * 64; f < part * 64 + 64; f++) {
                float w = W1[c * (NH * HD) + h * HD + f];
                s = fmaf(w, as1[h * HD + f], s);
                d = fmaf(w, ad1[h * HD + f], d);
            }
            sv[t] = s;
            sd[t] = d;
        }
        __syncthreads();
        if (t < 112) {
            g_vs[t] = sv[2 * t] + sv[2 * t + 1];
            g_vd[t] = sd[2 * t] + sd[2 * t + 1];
        }
    }
    grid_bar(&g_ta, HB);
    // phase 2: histogram (deg starts zero: static init / self-clean in scan)
    const int is64 = g_is64;
#pragma unroll
    for (int k = 0; k < 2; k++) {
        int i = base + k * (HB * 256);
        if (i < ET) {
            int dst = (i < NE) ? load_edge(ei, NE + i, is64) : (i - NE);
            atomicAdd(&g_deg[dst], 1);
        }
    }
}

__device__ __forceinline__ int block_scan_256(int v, int t) {
    __shared__ int wt[8];
    int lane = t & 31, w = t >> 5;
    int s = v;
#pragma unroll
    for (int o = 1; o < 32; o <<= 1) {
        int u = __shfl_up_sync(0xffffffffu, s, o);
        if (lane >= o) s += u;
    }
    if (lane == 31) wt[w] = s;
    __syncthreads();
    if (t < 8) {
        int u = wt[t];
#pragma unroll
        for (int o = 1; o < 8; o <<= 1) {
            int x = __shfl_up_sync(0xffu, u, o);
            if (t >= o) u += x;
        }
        wt[t] = u;
    }
    __syncthreads();
    return s + (w > 0 ? wt[w - 1] : 0);  // inclusive
}

// block-local exclusive scan; last-arriving block scans block sums.
// Also self-cleans g_deg for the next graph replay.
__global__ void k_scanAB() {
    __shared__ int lastsh;
    int t = threadIdx.x;
    int i = blockIdx.x * 256 + t;
    int v = 0;
    if (i < NN) {
        v = g_deg[i];
        g_deg[i] = 0;  // self-clean
    }
    int incl = block_scan_256(v, t);
    if (i < NN) g_rowptr[i] = incl - v;
    if (t == 255) g_bsum[blockIdx.x] = incl;
    __threadfence();
    __syncthreads();
    if (t == 0) lastsh = ((atomicAdd(&g_tick, 1) % NB) == NB - 1);
    __syncthreads();
    if (lastsh) {
        __threadfence();
        int u = (t < NB) ? *((volatile int*)&g_bsum[t]) : 0;
        int incl2 = block_scan_256(u, t);
        if (t < NB) g_boff[t] = incl2 - u;
        if (t == NB - 1) g_rowptr[NN] = incl2;
    }
}

// Fused: scan fixup + cursor init + attention scalars + padded x copy
//        | grid barrier | CSR scatter.  196 blocks -> all resident.
__global__ void k_alphaSc(const float* __restrict__ x, const void* __restrict__ ei) {
    __shared__ float vs[IC * NH], vd[IC * NH];
    int t = threadIdx.x;
    if (t < IC * NH) {
        vs[t] = g_vs[t];
        vd[t] = g_vd[t];
    }
    __syncthreads();
    int n = blockIdx.x * 256 + t;
    if (n < NN) {
        int r = g_rowptr[n] + g_boff[blockIdx.x];
        g_rowptr[n] = r;
        g_cursor[n] = r;
        float xr[IC];
#pragma unroll
        for (int c = 0; c < IC; c++) xr[c] = x[n * IC + c];
        float4 xv;
        xv.x = xr[0]; xv.y = xr[1]; xv.z = xr[2]; xv.w = xr[3];
        g_x16[4 * n + 0] = xv;
        xv.x = xr[4]; xv.y = xr[5]; xv.z = xr[6]; xv.w = xr[7];
        g_x16[4 * n + 1] = xv;
        xv.x = xr[8]; xv.y = xr[9]; xv.z = xr[10]; xv.w = xr[11];
        g_x16[4 * n + 2] = xv;
        xv.x = xr[12]; xv.y = xr[13]; xv.z = 0.f; xv.w = 0.f;
        g_x16[4 * n + 3] = xv;
        float a[NH], d[NH];
#pragma unroll
        for (int h = 0; h < NH; h++) {
            float s = 0.f, dd = 0.f;
#pragma unroll
            for (int c = 0; c < IC; c++) {
                s = fmaf(xr[c], vs[c * NH + h], s);
                dd = fmaf(xr[c], vd[c * NH + h], dd);
            }
            a[h] = s;
            d[h] = dd;
        }
        g_as4[n] = make_float4(a[0], a[1], a[2], a[3]);
        g_as4[NN + n] = make_float4(a[4], a[5], a[6], a[7]);
        g_ad4[n] = make_float4(d[0], d[1], d[2], d[3]);
        g_ad4[NN + n] = make_float4(d[4], d[5], d[6], d[7]);
    }
    grid_bar(&g_tb, NB);
    // phase 2: scatter edges into CSR
    const int is64 = g_is64;
    const int stride = NB * 256;
    for (int i = blockIdx.x * 256 + t; i < ET; i += stride) {
        int src, dst;
        if (i < NE) {
            src = load_edge(ei, i, is64);
            dst = load_edge(ei, NE + i, is64);
        } else {
            src = i - NE;
            dst = i - NE;
        }
        int pos = atomicAdd(&g_cursor[dst], 1);
        g_col[pos] = src;
    }
}

// Aggregation: thread = node, 4 heads per thread (blockIdx.y = head half).
__global__ void __launch_bounds__(256) k_agg() {
    int t = threadIdx.x;
    int n = blockIdx.x * 256 + t;
    if (n >= NN) return;
    const int half = blockIdx.y;
    const float4 adn = g_ad4[half * NN + n];
    const int r0 = g_rowptr[n], r1 = g_rowptr[n + 1];
    float ss0 = 0.f, ss1 = 0.f, ss2 = 0.f, ss3 = 0.f;
    float zc[4][IC];
#pragma unroll
    for (int j = 0; j < 4; j++)
#pragma unroll
        for (int c = 0; c < IC; c++) zc[j][c] = 0.f;
    for (int e = r0; e < r1; e++) {
        int s = g_col[e];
        float4 a4 = g_as4[half * NN + s];
        float w0 = __expf(lrelu(a4.x + adn.x));
        float w1 = __expf(lrelu(a4.y + adn.y));
        float w2 = __expf(lrelu(a4.z + adn.z));
        float w3 = __expf(lrelu(a4.w + adn.w));
        ss0 += w0; ss1 += w1; ss2 += w2; ss3 += w3;
        float4 xa = g_x16[4 * s + 0];
        float4 xb = g_x16[4 * s + 1];
        float4 xc = g_x16[4 * s + 2];
        float4 xd = g_x16[4 * s + 3];
        float xr[IC] = {xa.x, xa.y, xa.z, xa.w, xb.x, xb.y, xb.z, xb.w,
                        xc.x, xc.y, xc.z, xc.w, xd.x, xd.y};
#pragma unroll
        for (int c = 0; c < IC; c++) {
            zc[0][c] = fmaf(w0, xr[c], zc[0][c]);
            zc[1][c] = fmaf(w1, xr[c], zc[1][c]);
            zc[2][c] = fmaf(w2, xr[c], zc[2][c]);
            zc[3][c] = fmaf(w3, xr[c], zc[3][c]);
        }
    }
    float inv[4];
    inv[0] = 1.f / (ss0 + 1e-16f);
    inv[1] = 1.f / (ss1 + 1e-16f);
    inv[2] = 1.f / (ss2 + 1e-16f);
    inv[3] = 1.f / (ss3 + 1e-16f);
#pragma unroll
    for (int j = 0; j < 4; j++) {
        const int h = half * 4 + j;
#pragma unroll
        for (int c = 0; c < IC; c++)
            g_zT[(h * IC + c) * NN + n] = zc[j][c] * inv[j];
    }
}

// Projection: thread = node (256/block for 2x occupancy); blockIdx.y = head half.
#define SW_ROW 20
__global__ void __launch_bounds__(256)
k_proj(const float* __restrict__ W1, const float* __restrict__ b1,
       const float* __restrict__ W2) {
    __shared__ ull sw[256][SW_ROW];  // 40960 B
    const int t = threadIdx.x;
    const int half = blockIdx.y;
    {
        int p = t;
        int op = half * 256 + p;
        int o0 = 2 * op, o1 = o0 + 1;
#pragma unroll
        for (int c = 0; c < IC; c++)
            sw[p][c] = pk2(W1[c * (NH * HD) + o0], W1[c * (NH * HD) + o1]);
        sw[p][14] = pk2(b1[o0], b1[o1]);
        sw[p][15] = 0;
        sw[p][16] = pk2(W2[o0 * OD + 0], W2[o0 * OD + 1]);
        sw[p][17] = pk2(W2[o0 * OD + 2], W2[o0 * OD + 3]);
        sw[p][18] = pk2(W2[o1 * OD + 0], W2[o1 * OD + 1]);
        sw[p][19] = pk2(W2[o1 * OD + 2], W2[o1 * OD + 3]);
    }
    __syncthreads();
    const int n = blockIdx.x * 256 + t;
    if (n >= NN) return;

    ull h2a = 0, h2b = 0;
#pragma unroll
    for (int hl = 0; hl < 4; hl++) {
        const int h = half * 4 + hl;
        ull zz[IC];
#pragma unroll
        for (int c = 0; c < IC; c++) {
            float zv = g_zT[(h * IC + c) * NN + n];
            zz[c] = pk2(zv, zv);
        }
#pragma unroll 4
        for (int q = 0; q < 64; q++) {
            const int p = hl * 64 + q;
            const ulonglong2* row = (const ulonglong2*)&sw[p][0];
            ull acc0 = sw[p][14];
            ull acc1 = 0;
#pragma unroll
            for (int cc = 0; cc < 7; cc++) {
                ulonglong2 w = row[cc];
                acc0 = fma2(zz[2 * cc], w.x, acc0);
                acc1 = fma2(zz[2 * cc + 1], w.y, acc1);
            }
            acc0 = add2(acc0, acc1);
            float t0, t1;
            upk2(acc0, t0, t1);
            float e0 = (t0 > 0.f) ? t0 : (__expf(t0) - 1.f);
            float e1 = (t1 > 0.f) ? t1 : (__expf(t1) - 1.f);
            ull aa0 = pk2(e0, e0), aa1 = pk2(e1, e1);
            ulonglong2 w2a = *(const ulonglong2*)&sw[p][16];
            ulonglong2 w2b = *(const ulonglong2*)&sw[p][18];
            h2a = fma2(aa0, w2a.x, h2a);
            h2b = fma2(aa0, w2a.y, h2b);
            h2a = fma2(aa1, w2b.x, h2a);
            h2b = fma2(aa1, w2b.y, h2b);
        }
    }
    float4 o4;
    upk2(h2a, o4.x, o4.y);
    upk2(h2b, o4.z, o4.w);
    g_h2p[half * NN + n] = o4;
}

// Layer-2: thread = destination node; combines head-half partials on the fly.
__global__ void k_layer2(float* __restrict__ out, const float* __restrict__ b2,
                         const float* __restrict__ as2, const float* __restrict__ ad2) {
    int n = blockIdx.x * blockDim.x + threadIdx.x;
    if (n >= NN) return;
    const float s0 = __ldg(as2 + 0), s1 = __ldg(as2 + 1),
                s2 = __ldg(as2 + 2), s3 = __ldg(as2 + 3);
    float4 pa = g_h2p[n], pb = g_h2p[NN + n];
    float hx = pa.x + pb.x, hy = pa.y + pb.y, hz = pa.z + pb.z, hw = pa.w + pb.w;
    const float adn = hx * __ldg(ad2 + 0) + hy * __ldg(ad2 + 1) +
                      hz * __ldg(ad2 + 2) + hw * __ldg(ad2 + 3);
    const int r0 = g_rowptr[n], r1 = g_rowptr[n + 1];
    float ss = 0.f, ax = 0.f, ay = 0.f, az = 0.f, aw = 0.f;
    for (int e = r0; e < r1; e++) {
        int s = g_col[e];
        float4 qa = g_h2p[s], qb = g_h2p[NN + s];
        float vx = qa.x + qb.x, vy = qa.y + qb.y,
              vz = qa.z + qb.z, vw = qa.w + qb.w;
        float v = vx * s0 + vy * s1 + vz * s2 + vw * s3 + adn;
        v = lrelu(v);
        float w = __expf(v);
        ss += w;
        ax = fmaf(w, vx, ax);
        ay = fmaf(w, vy, ay);
        az = fmaf(w, vz, az);
        aw = fmaf(w, vw, aw);
    }
    float inv = 1.f / (ss + 1e-16f);
    float4 o4;
    o4.x = ax * inv + __ldg(b2 + 0);
    o4.y = ay * inv + __ldg(b2 + 1);
    o4.z = az * inv + __ldg(b2 + 2);
    o4.w = aw * inv + __ldg(b2 + 3);
    ((float4*)out)[n] = o4;
}

extern "C" void kernel_launch(void* const* d_in, const int* in_sizes, int n_in,
                              void* d_out, int out_size) {
    const float* x   = (const float*)d_in[0];
    const void*  ei  = d_in[1];
    const float* W1  = (const float*)d_in[2];
    const float* as1 = (const float*)d_in[3];
    const float* ad1 = (const float*)d_in[4];
    const float* b1  = (const float*)d_in[5];
    const float* W2  = (const float*)d_in[6];
    const float* as2 = (const float*)d_in[7];
    const float* ad2 = (const float*)d_in[8];
    const float* b2  = (const float*)d_in[9];
    float* out = (float*)d_out;

    k_histF<<<HB, 256>>>(ei, W1, as1, ad1);
    k_scanAB<<<NB, 256>>>();
    k_alphaSc<<<NB, 256>>>(x, ei);
    dim3 ag(NB, 2);
    k_agg<<<ag, 256>>>();
    dim3 pg(NB, 2);
    k_proj<<<pg, 256>>>(W1, b1, W2);
    k_layer2<<<NB, 256>>>(out, b2, as2, ad2);
}